// round 1
// baseline (speedup 1.0000x reference)
#include <cuda_runtime.h>
#include <cuda_bf16.h>
#include <cstdint>

// Problem constants
#define N_NODE 40000
#define N_EDGE 320000
#define DIM    1024

// ---------------- device scratch (no cudaMalloc allowed) ----------------
__device__ int   g_deg[N_NODE];
__device__ int   g_offs[N_NODE + 1];
__device__ int   g_cursor[N_NODE];
__device__ int   g_sorted_src[N_EDGE];
__device__ float g_agg[(size_t)N_NODE * DIM];   // 160 MB reused across relations

// ---------------- small helpers ----------------
__device__ __forceinline__ uint32_t f2tf32(float x) {
    uint32_t r;
    asm("cvt.rna.tf32.f32 %0, %1;" : "=r"(r) : "f"(x));
    return r;
}

__device__ __forceinline__ void mma_tf32(float& c0, float& c1, float& c2, float& c3,
                                         uint32_t a0, uint32_t a1, uint32_t a2, uint32_t a3,
                                         uint32_t b0, uint32_t b1) {
    asm volatile(
        "mma.sync.aligned.m16n8k8.row.col.f32.tf32.tf32.f32 "
        "{%0,%1,%2,%3}, {%4,%5,%6,%7}, {%8,%9}, {%0,%1,%2,%3};"
        : "+f"(c0), "+f"(c1), "+f"(c2), "+f"(c3)
        : "r"(a0), "r"(a1), "r"(a2), "r"(a3), "r"(b0), "r"(b1));
}

// ---------------- sort-by-dst pipeline ----------------
__global__ void zero_deg_kernel() {
    int i = blockIdx.x * blockDim.x + threadIdx.x;
    if (i < N_NODE) g_deg[i] = 0;
}

__global__ void hist_kernel(const int* __restrict__ dst) {
    int i = blockIdx.x * blockDim.x + threadIdx.x;
    if (i < N_EDGE) atomicAdd(&g_deg[dst[i]], 1);
}

// single-block exclusive scan of g_deg -> g_offs (and g_cursor copy)
__global__ void scan_kernel() {
    __shared__ int sh[1024];
    __shared__ int carry;
    int t = threadIdx.x;
    if (t == 0) carry = 0;
    __syncthreads();
    for (int base = 0; base < N_NODE; base += 1024) {
        int idx = base + t;
        int v = (idx < N_NODE) ? g_deg[idx] : 0;
        sh[t] = v;
        __syncthreads();
        // Hillis-Steele inclusive scan
        #pragma unroll
        for (int off = 1; off < 1024; off <<= 1) {
            int x = (t >= off) ? sh[t - off] : 0;
            __syncthreads();
            sh[t] += x;
            __syncthreads();
        }
        int incl = sh[t];
        int excl = incl - v;
        int c = carry;                       // stable: updated only after barrier below
        if (idx < N_NODE) {
            g_offs[idx]   = c + excl;
            g_cursor[idx] = c + excl;
        }
        int total = sh[1023];
        __syncthreads();
        if (t == 0) carry = c + total;
        __syncthreads();
    }
    if (t == 0) g_offs[N_NODE] = carry;
}

__global__ void scatter_kernel(const int* __restrict__ src, const int* __restrict__ dst) {
    int i = blockIdx.x * blockDim.x + threadIdx.x;
    if (i < N_EDGE) {
        int pos = atomicAdd(&g_cursor[dst[i]], 1);
        g_sorted_src[pos] = src[i];
    }
}

// one block (256 threads) per destination node; each thread owns one float4 of the row
__global__ void aggregate_kernel(const float* __restrict__ xsrc) {
    int v = blockIdx.x;
    int beg = g_offs[v];
    int end = g_offs[v + 1];
    int t = threadIdx.x;

    float4 acc = make_float4(0.f, 0.f, 0.f, 0.f);
    const float4* xs = reinterpret_cast<const float4*>(xsrc);
    for (int e = beg; e < end; ++e) {
        int s = g_sorted_src[e];
        float4 r = xs[(size_t)s * (DIM / 4) + t];
        acc.x += r.x; acc.y += r.y; acc.z += r.z; acc.w += r.w;
    }
    int d = end - beg;
    float inv = 1.0f / (float)(d > 1 ? d : 1);
    acc.x *= inv; acc.y *= inv; acc.z *= inv; acc.w *= inv;
    reinterpret_cast<float4*>(g_agg)[(size_t)v * (DIM / 4) + t] = acc;
}

// ---------------- TF32 tensor-core GEMM: C[M,1024] = g_agg[M,1024] @ W[1024,1024] (+bias | +=) ----------------
// BM=128 BN=128 BK=16, 256 threads (8 warps: 2 m-rows x 4 n-cols), warp tile 64x32.
// Smem tiles are written in fragment-permuted order so the mainloop is conflict-free LDS.128/LDS.64.
template <int ACCUM>
__global__ __launch_bounds__(256, 2) void gemm_tf32_kernel(
    const float* __restrict__ Wm, const float* __restrict__ bias,
    float* __restrict__ C, int M)
{
    __shared__ uint32_t Asm[2048];  // 128x16 permuted
    __shared__ uint32_t Bsm[2048];  // 16x128 permuted

    const int t      = threadIdx.x;
    const int lane   = t & 31;
    const int warp   = t >> 5;
    const int warp_m = warp >> 2;   // 0..1
    const int warp_n = warp & 3;    // 0..3
    const int g      = lane >> 2;   // groupID
    const int tid4   = lane & 3;    // threadID_in_group
    const int bm     = blockIdx.y * 128;
    const int bn     = blockIdx.x * 128;

    float c[4][4][4];
    #pragma unroll
    for (int mt = 0; mt < 4; mt++)
        #pragma unroll
        for (int nt = 0; nt < 4; nt++)
            #pragma unroll
            for (int r = 0; r < 4; r++) c[mt][nt][r] = 0.f;

    for (int kt = 0; kt < DIM / 16; ++kt) {
        const int k0 = kt * 16;
        __syncthreads();
        // ---- stage A tile (128 rows x 16 k) into permuted smem ----
        #pragma unroll
        for (int i = 0; i < 2; i++) {
            int idx = t + i * 256;              // 0..511
            int m   = idx >> 2;                 // 0..127
            int kq  = idx & 3;                  // float4 index along k
            int gm  = bm + m;
            float4 va = (gm < M)
                ? reinterpret_cast<const float4*>(g_agg + (size_t)gm * DIM + k0)[kq]
                : make_float4(0.f, 0.f, 0.f, 0.f);
            float vv[4] = {va.x, va.y, va.z, va.w};
            #pragma unroll
            for (int j = 0; j < 4; j++) {
                int k      = kq * 4 + j;
                int wm     = m >> 6;
                int mtile  = (m & 63) >> 4;
                int r16    = m & 15;
                int gg     = r16 & 7;
                int rowh   = r16 >> 3;
                int kstep  = k >> 3;
                int kk     = k & 7;
                int ti     = kk & 3;
                int colh   = kk >> 2;
                int reg    = colh * 2 + rowh;
                int ln     = gg * 4 + ti;
                Asm[(((wm * 4 + mtile) * 2 + kstep) * 128) + ln * 4 + reg] = f2tf32(vv[j]);
            }
        }
        // ---- stage B tile (16 k x 128 n) into permuted smem ----
        #pragma unroll
        for (int i = 0; i < 2; i++) {
            int idx = t + i * 256;
            int kr  = idx >> 5;                 // 0..15
            int nq  = idx & 31;                 // float4 index along n
            float4 vb = reinterpret_cast<const float4*>(
                Wm + (size_t)(k0 + kr) * DIM + bn + nq * 4)[0];
            float vv[4] = {vb.x, vb.y, vb.z, vb.w};
            #pragma unroll
            for (int j = 0; j < 4; j++) {
                int n     = nq * 4 + j;
                int wn    = n >> 5;
                int ntile = (n & 31) >> 3;
                int gg    = n & 7;
                int kstep = kr >> 3;
                int kk    = kr & 7;
                int ti    = kk & 3;
                int reg   = kk >> 2;
                int ln    = gg * 4 + ti;
                Bsm[(((wn * 4 + ntile) * 2 + kstep) * 64) + ln * 2 + reg] = f2tf32(vv[j]);
            }
        }
        __syncthreads();
        // ---- compute: 2 k-steps of m16n8k8 ----
        #pragma unroll
        for (int ks = 0; ks < 2; ks++) {
            uint32_t a[4][4];
            #pragma unroll
            for (int mt = 0; mt < 4; mt++) {
                const uint4 va = *reinterpret_cast<const uint4*>(
                    &Asm[(((warp_m * 4 + mt) * 2 + ks) * 128) + lane * 4]);
                a[mt][0] = va.x; a[mt][1] = va.y; a[mt][2] = va.z; a[mt][3] = va.w;
            }
            uint32_t b[4][2];
            #pragma unroll
            for (int nt = 0; nt < 4; nt++) {
                const uint2 vb = *reinterpret_cast<const uint2*>(
                    &Bsm[(((warp_n * 4 + nt) * 2 + ks) * 64) + lane * 2]);
                b[nt][0] = vb.x; b[nt][1] = vb.y;
            }
            #pragma unroll
            for (int mt = 0; mt < 4; mt++)
                #pragma unroll
                for (int nt = 0; nt < 4; nt++)
                    mma_tf32(c[mt][nt][0], c[mt][nt][1], c[mt][nt][2], c[mt][nt][3],
                             a[mt][0], a[mt][1], a[mt][2], a[mt][3],
                             b[nt][0], b[nt][1]);
        }
    }

    // ---- epilogue ----
    #pragma unroll
    for (int mt = 0; mt < 4; mt++) {
        int r0 = bm + warp_m * 64 + mt * 16 + g;
        int r1 = r0 + 8;
        #pragma unroll
        for (int nt = 0; nt < 4; nt++) {
            int col = bn + warp_n * 32 + nt * 8 + tid4 * 2;
            float bv0 = 0.f, bv1 = 0.f;
            if (!ACCUM) { bv0 = bias[col]; bv1 = bias[col + 1]; }
            if (r0 < M) {
                float* p = &C[(size_t)r0 * DIM + col];
                if (ACCUM) { p[0] += c[mt][nt][0]; p[1] += c[mt][nt][1]; }
                else       { p[0]  = c[mt][nt][0] + bv0; p[1] = c[mt][nt][1] + bv1; }
            }
            if (r1 < M) {
                float* p = &C[(size_t)r1 * DIM + col];
                if (ACCUM) { p[0] += c[mt][nt][2]; p[1] += c[mt][nt][3]; }
                else       { p[0]  = c[mt][nt][2] + bv0; p[1] = c[mt][nt][3] + bv1; }
            }
        }
    }
}

// ---------------- launch ----------------
static void run_relation(const float* xsrc, const int* src, const int* dst,
                         const float* W, const float* b, float* out, int accum)
{
    zero_deg_kernel<<<(N_NODE + 255) / 256, 256>>>();
    hist_kernel<<<(N_EDGE + 255) / 256, 256>>>(dst);
    scan_kernel<<<1, 1024>>>();
    scatter_kernel<<<(N_EDGE + 255) / 256, 256>>>(src, dst);
    aggregate_kernel<<<N_NODE, 256>>>(xsrc);
    dim3 grid(DIM / 128, (N_NODE + 127) / 128);
    if (accum) gemm_tf32_kernel<1><<<grid, 256>>>(W, b, out, N_NODE);
    else       gemm_tf32_kernel<0><<<grid, 256>>>(W, b, out, N_NODE);
}

extern "C" void kernel_launch(void* const* d_in, const int* in_sizes, int n_in,
                              void* d_out, int out_size)
{
    const float* x_drug = (const float*)d_in[0];
    const float* x_prot = (const float*)d_in[1];
    const float* W_ddi  = (const float*)d_in[2];
    const float* b_ddi  = (const float*)d_in[3];
    const float* W_dpi  = (const float*)d_in[4];
    const float* b_dpi  = (const float*)d_in[5];
    const float* W_ppi  = (const float*)d_in[6];
    const float* b_ppi  = (const float*)d_in[7];
    const int* src_ddi  = (const int*)d_in[8];
    const int* dst_ddi  = (const int*)d_in[9];
    const int* src_dpi  = (const int*)d_in[10];
    const int* dst_dpi  = (const int*)d_in[11];
    const int* src_ppi  = (const int*)d_in[12];
    const int* dst_ppi  = (const int*)d_in[13];

    float* out_drug = (float*)d_out;
    float* out_prot = out_drug + (size_t)N_NODE * DIM;

    // drug <- ddi(drug)
    run_relation(x_drug, src_ddi, dst_ddi, W_ddi, b_ddi, out_drug, /*accum=*/0);
    // prot <- dpi(drug) + ppi(prot)
    run_relation(x_drug, src_dpi, dst_dpi, W_dpi, b_dpi, out_prot, /*accum=*/0);
    run_relation(x_prot, src_ppi, dst_ppi, W_ppi, b_ppi, out_prot, /*accum=*/1);
}